// round 2
// baseline (speedup 1.0000x reference)
#include <cuda_runtime.h>

#define CEPS 1e-5f

// ---------------- device scratch (no allocation allowed) ----------------
__device__ float d_imT[8 * 256 * 2048];          // [b][hw][cin]
__device__ float d_x[8 * 256 * 1024];            // [b][hw][c2]
__device__ float d_wT[9 * 1024 * 256];           // [tap][ci][o] BN-folded
__device__ float d_tb[256];                      // folded conv bias
__device__ float d_r[512 * 49 * 1024];           // roi tiles [roi][pix][c]
__device__ float d_r1[512 * 12544];              // conv out, flat (o*49+p)
__device__ float d_fcp[16 * 512 * 1024];         // FC split-K partials
__device__ float d_feats[512 * 1280];
__device__ float d_U[512 * 1280];
__device__ float d_V[512 * 1280];
__device__ float d_h1[32768u * 1280u];
__device__ float d_h2[32768u * 1280u];
__device__ float d_gp[256 * 1280];               // g3 per-Mblock col sums

// ---------------- transpose im_feat [8][2048][256] -> [8][256][2048] ----
__global__ void transpose_bchw(const float* __restrict__ in, float* __restrict__ out) {
    __shared__ float tile[32][33];
    int b = blockIdx.z;
    int p0 = blockIdx.x * 32;   // hw
    int c0 = blockIdx.y * 32;   // channel
    int tx = threadIdx.x, ty = threadIdx.y;
    const float* ip = in + (long long)b * 2048 * 256;
    #pragma unroll
    for (int i = 0; i < 32; i += 8)
        tile[ty + i][tx] = ip[(c0 + ty + i) * 256 + p0 + tx];
    __syncthreads();
    float* op = out + (long long)b * 256 * 2048;
    #pragma unroll
    for (int i = 0; i < 32; i += 8)
        op[(p0 + ty + i) * 2048 + c0 + tx] = tile[tx][ty + i];
}

// ---------------- conv weight prep: wT[t][ci][o] = conv_w[o][ci][t]*s[o] ---
__global__ void prep_convw(const float* __restrict__ cw, const float* __restrict__ g,
                           const float* __restrict__ v, float* __restrict__ wT) {
    int i = blockIdx.x * 256 + threadIdx.x;   // < 9*1024*256
    int o = i & 255;
    int ci = (i >> 8) & 1023;
    int t = i >> 18;
    float s = g[o] * rsqrtf(v[o] + CEPS);
    wT[i] = cw[o * 9216 + ci * 9 + t] * s;
}

__global__ void prep_tb(const float* __restrict__ cb, const float* __restrict__ g,
                        const float* __restrict__ b, const float* __restrict__ m,
                        const float* __restrict__ v, float* __restrict__ tb) {
    int o = threadIdx.x;
    float s = g[o] * rsqrtf(v[o] + CEPS);
    tb[o] = (cb[o] - m[o]) * s + b[o];
}

// ---------------- generic GEMM: C = A[M,K] @ B[N,K]^T (+bias)(+relu) -----
// EPI: 0 store, 1 +bias store, 2 +bias relu store, 3 +bias relu colsum only
template<int EPI>
__global__ void __launch_bounds__(256, 2) gemm128(
    const float* __restrict__ A, int lda, long long aZ,
    const float* __restrict__ B, int ldb, long long bZ,
    const float* __restrict__ bias,
    float* __restrict__ C, int ldc, long long cZ,
    int K, float* __restrict__ colsum)
{
    __shared__ float As[2][16][132];
    __shared__ float Bs[2][16][132];
    const int tid = threadIdx.x;
    const int z = blockIdx.z;
    const int mB = blockIdx.x * 128, nB = blockIdx.y * 128;
    A += (long long)z * aZ;
    B += (long long)z * bZ;

    const int lr = tid >> 2;            // 0..63
    const int lk = (tid & 3) << 2;      // 0,4,8,12
    const float* Ag0 = A + (long long)(mB + lr) * lda + lk;
    const float* Ag1 = Ag0 + 64LL * lda;
    const float* Bg0 = B + (long long)(nB + lr) * ldb + lk;
    const float* Bg1 = Bg0 + 64LL * ldb;

    const int ty = tid >> 4, tx = tid & 15;
    float acc[8][8];
    #pragma unroll
    for (int i = 0; i < 8; i++)
        #pragma unroll
        for (int j = 0; j < 8; j++) acc[i][j] = 0.f;

    // initial fill
    {
        float4 a0 = *(const float4*)Ag0;
        float4 a1 = *(const float4*)Ag1;
        float4 b0 = *(const float4*)Bg0;
        float4 b1 = *(const float4*)Bg1;
        As[0][lk + 0][lr] = a0.x; As[0][lk + 1][lr] = a0.y; As[0][lk + 2][lr] = a0.z; As[0][lk + 3][lr] = a0.w;
        As[0][lk + 0][lr + 64] = a1.x; As[0][lk + 1][lr + 64] = a1.y; As[0][lk + 2][lr + 64] = a1.z; As[0][lk + 3][lr + 64] = a1.w;
        Bs[0][lk + 0][lr] = b0.x; Bs[0][lk + 1][lr] = b0.y; Bs[0][lk + 2][lr] = b0.z; Bs[0][lk + 3][lr] = b0.w;
        Bs[0][lk + 0][lr + 64] = b1.x; Bs[0][lk + 1][lr + 64] = b1.y; Bs[0][lk + 2][lr + 64] = b1.z; Bs[0][lk + 3][lr + 64] = b1.w;
    }
    __syncthreads();

    int buf = 0;
    for (int kt = 0; kt < K; kt += 16) {
        float4 a0, a1, b0, b1;
        const bool more = (kt + 16) < K;
        if (more) {
            a0 = *(const float4*)(Ag0 + kt + 16);
            a1 = *(const float4*)(Ag1 + kt + 16);
            b0 = *(const float4*)(Bg0 + kt + 16);
            b1 = *(const float4*)(Bg1 + kt + 16);
        }
        #pragma unroll
        for (int k = 0; k < 16; k++) {
            float4 av0 = *(const float4*)&As[buf][k][ty * 8];
            float4 av1 = *(const float4*)&As[buf][k][ty * 8 + 4];
            float4 bv0 = *(const float4*)&Bs[buf][k][tx * 8];
            float4 bv1 = *(const float4*)&Bs[buf][k][tx * 8 + 4];
            float a[8] = {av0.x, av0.y, av0.z, av0.w, av1.x, av1.y, av1.z, av1.w};
            float b[8] = {bv0.x, bv0.y, bv0.z, bv0.w, bv1.x, bv1.y, bv1.z, bv1.w};
            #pragma unroll
            for (int i = 0; i < 8; i++)
                #pragma unroll
                for (int j = 0; j < 8; j++)
                    acc[i][j] += a[i] * b[j];
        }
        if (more) {
            int nb2 = buf ^ 1;
            As[nb2][lk + 0][lr] = a0.x; As[nb2][lk + 1][lr] = a0.y; As[nb2][lk + 2][lr] = a0.z; As[nb2][lk + 3][lr] = a0.w;
            As[nb2][lk + 0][lr + 64] = a1.x; As[nb2][lk + 1][lr + 64] = a1.y; As[nb2][lk + 2][lr + 64] = a1.z; As[nb2][lk + 3][lr + 64] = a1.w;
            Bs[nb2][lk + 0][lr] = b0.x; Bs[nb2][lk + 1][lr] = b0.y; Bs[nb2][lk + 2][lr] = b0.z; Bs[nb2][lk + 3][lr] = b0.w;
            Bs[nb2][lk + 0][lr + 64] = b1.x; Bs[nb2][lk + 1][lr + 64] = b1.y; Bs[nb2][lk + 2][lr + 64] = b1.z; Bs[nb2][lk + 3][lr + 64] = b1.w;
        }
        __syncthreads();
        buf ^= 1;
    }

    const int colBase = nB + tx * 8;
    if (EPI == 3) {
        float bj[8];
        #pragma unroll
        for (int j = 0; j < 8; j++) bj[j] = bias[colBase + j];
        float cs[8];
        #pragma unroll
        for (int j = 0; j < 8; j++) {
            cs[j] = 0.f;
            #pragma unroll
            for (int i = 0; i < 8; i++) cs[j] += fmaxf(acc[i][j] + bj[j], 0.f);
        }
        float* red = &As[0][0][0];   // safe: loop ended with __syncthreads
        #pragma unroll
        for (int j = 0; j < 8; j++) red[ty * 128 + tx * 8 + j] = cs[j];
        __syncthreads();
        for (int s = 8; s > 0; s >>= 1) {
            if (ty < s) {
                #pragma unroll
                for (int j = 0; j < 8; j++)
                    red[ty * 128 + tx * 8 + j] += red[(ty + s) * 128 + tx * 8 + j];
            }
            __syncthreads();
        }
        if (ty == 0) {
            #pragma unroll
            for (int j = 0; j < 8; j++)
                colsum[(long long)blockIdx.x * (gridDim.y * 128) + colBase + j] = red[tx * 8 + j];
        }
    } else {
        float bj[8];
        #pragma unroll
        for (int j = 0; j < 8; j++) bj[j] = (EPI >= 1) ? bias[colBase + j] : 0.f;
        float* Cz = C + (long long)z * cZ;
        #pragma unroll
        for (int i = 0; i < 8; i++) {
            long long r = mB + ty * 8 + i;
            float o[8];
            #pragma unroll
            for (int j = 0; j < 8; j++) {
                float v = acc[i][j] + bj[j];
                if (EPI == 2) v = fmaxf(v, 0.f);
                o[j] = v;
            }
            *(float4*)&Cz[r * ldc + colBase] = make_float4(o[0], o[1], o[2], o[3]);
            *(float4*)&Cz[r * ldc + colBase + 4] = make_float4(o[4], o[5], o[6], o[7]);
        }
    }
}

// ---------------- ROIAlign gather: one block per (roi, bin) -------------
__global__ void roialign_kernel(const float* __restrict__ x,     // [8][256][1024]
                                const float* __restrict__ boxes, // [512][4]
                                float* __restrict__ out)         // [512][49][1024]
{
    int blk = blockIdx.x;     // 0..25087
    int n = blk / 49;
    int bin = blk - n * 49;
    int by = bin / 7, bx = bin - by * 7;
    int b = n >> 6;
    const float* roi = boxes + n * 4;
    float x1 = roi[0] * (1.f / 32.f) - 0.5f;
    float y1 = roi[1] * (1.f / 32.f) - 0.5f;
    float bw = (roi[2] - roi[0]) * (1.f / 32.f) * (1.f / 7.f);
    float bh = (roi[3] - roi[1]) * (1.f / 32.f) * (1.f / 7.f);

    int pidx[16];
    float pw[16];
    int cnt = 0;
    #pragma unroll
    for (int sy = 0; sy < 2; sy++) {
        float ys = y1 + bh * ((float)by + (sy + 0.5f) * 0.5f);
        bool vy = (ys >= -1.f) && (ys <= 16.f);
        float v = fmaxf(ys, 0.f);
        int lo = (int)floorf(v);
        int yl, yh; float wy;
        if (lo >= 15) { yl = 15; yh = 15; wy = 0.f; }
        else { yl = lo; yh = lo + 1; wy = v - (float)lo; }
        #pragma unroll
        for (int sx = 0; sx < 2; sx++) {
            float xs = x1 + bw * ((float)bx + (sx + 0.5f) * 0.5f);
            bool vx = (xs >= -1.f) && (xs <= 16.f);
            float u = fmaxf(xs, 0.f);
            int lo2 = (int)floorf(u);
            int xl, xh; float wx;
            if (lo2 >= 15) { xl = 15; xh = 15; wx = 0.f; }
            else { xl = lo2; xh = lo2 + 1; wx = u - (float)lo2; }
            float m = (vy && vx) ? 0.25f : 0.f;
            pidx[cnt] = yl * 16 + xl; pw[cnt] = (1.f - wy) * (1.f - wx) * m; cnt++;
            pidx[cnt] = yl * 16 + xh; pw[cnt] = (1.f - wy) * wx * m;         cnt++;
            pidx[cnt] = yh * 16 + xl; pw[cnt] = wy * (1.f - wx) * m;         cnt++;
            pidx[cnt] = yh * 16 + xh; pw[cnt] = wy * wx * m;                 cnt++;
        }
    }

    const float* xb = x + ((long long)b << 18);   // b*256*1024
    int c = threadIdx.x * 4;
    float4 acc = make_float4(0.f, 0.f, 0.f, 0.f);
    #pragma unroll
    for (int t = 0; t < 16; t++) {
        float4 vv = *(const float4*)(xb + (pidx[t] << 10) + c);
        acc.x += pw[t] * vv.x; acc.y += pw[t] * vv.y;
        acc.z += pw[t] * vv.z; acc.w += pw[t] * vv.w;
    }
    *(float4*)(out + ((long long)blk << 10) + c) = acc;
}

// ---------------- conv3x3 implicit GEMM (BN+ReLU folded) ----------------
__global__ void __launch_bounds__(256, 2) conv_gemm(
    const float* __restrict__ R,    // [512][49][1024]
    const float* __restrict__ wT,   // [9][1024][256]
    const float* __restrict__ tb,   // [256]
    float* __restrict__ O)          // [512][12544] flat (o*49+p)
{
    __shared__ float As[2][16][132];
    __shared__ float Bs[2][16][132];
    const int tid = threadIdx.x;
    const int mB = blockIdx.x * 128, nB = blockIdx.y * 128;
    const int lr = tid >> 2, lk = (tid & 3) << 2;
    const int bk = tid >> 4, bn = (tid & 15) << 3;
    const int ty = tid >> 4, tx = tid & 15;

    int off0[9], off1[9];
    {
        int gr0 = mB + lr, gr1 = gr0 + 64;
        int n0 = gr0 / 49, p0 = gr0 - n0 * 49, y0 = p0 / 7, x0 = p0 - y0 * 7;
        int n1 = gr1 / 49, p1 = gr1 - n1 * 49, y1 = p1 / 7, x1 = p1 - y1 * 7;
        #pragma unroll
        for (int t = 0; t < 9; t++) {
            int kh = t / 3 - 1, kw = t % 3 - 1;
            int iy = y0 + kh, ix = x0 + kw;
            off0[t] = (iy >= 0 && iy < 7 && ix >= 0 && ix < 7) ? ((n0 * 49 + iy * 7 + ix) << 10) : -1;
            iy = y1 + kh; ix = x1 + kw;
            off1[t] = (iy >= 0 && iy < 7 && ix >= 0 && ix < 7) ? ((n1 * 49 + iy * 7 + ix) << 10) : -1;
        }
    }

    float acc[8][8];
    #pragma unroll
    for (int i = 0; i < 8; i++)
        #pragma unroll
        for (int j = 0; j < 8; j++) acc[i][j] = 0.f;

    const float4 z4 = make_float4(0.f, 0.f, 0.f, 0.f);
    auto ldA = [&](int q, float4& a0, float4& a1) {
        int t = q >> 6;
        int kk = ((q & 63) << 4) + lk;
        a0 = (off0[t] >= 0) ? *(const float4*)(R + off0[t] + kk) : z4;
        a1 = (off1[t] >= 0) ? *(const float4*)(R + off1[t] + kk) : z4;
    };
    auto ldB = [&](int q, float4& b0, float4& b1) {
        int t = q >> 6;
        int kk = ((q & 63) << 4) + bk;
        const float* p = wT + (t << 18) + kk * 256 + nB + bn;
        b0 = *(const float4*)p;
        b1 = *(const float4*)(p + 4);
    };
    auto stA = [&](int bu, float4 a0, float4 a1) {
        As[bu][lk + 0][lr] = a0.x; As[bu][lk + 1][lr] = a0.y; As[bu][lk + 2][lr] = a0.z; As[bu][lk + 3][lr] = a0.w;
        As[bu][lk + 0][lr + 64] = a1.x; As[bu][lk + 1][lr + 64] = a1.y; As[bu][lk + 2][lr + 64] = a1.z; As[bu][lk + 3][lr + 64] = a1.w;
    };
    auto stB = [&](int bu, float4 b0, float4 b1) {
        *(float4*)&Bs[bu][bk][bn] = b0;
        *(float4*)&Bs[bu][bk][bn + 4] = b1;
    };

    {
        float4 a0, a1, b0, b1;
        ldA(0, a0, a1); ldB(0, b0, b1);
        stA(0, a0, a1); stB(0, b0, b1);
    }
    __syncthreads();

    int buf = 0;
    for (int q = 0; q < 576; q++) {
        float4 a0, a1, b0, b1;
        const bool more = (q + 1) < 576;
        if (more) { ldA(q + 1, a0, a1); ldB(q + 1, b0, b1); }
        #pragma unroll
        for (int k = 0; k < 16; k++) {
            float4 av0 = *(const float4*)&As[buf][k][ty * 8];
            float4 av1 = *(const float4*)&As[buf][k][ty * 8 + 4];
            float4 bv0 = *(const float4*)&Bs[buf][k][tx * 8];
            float4 bv1 = *(const float4*)&Bs[buf][k][tx * 8 + 4];
            float a[8] = {av0.x, av0.y, av0.z, av0.w, av1.x, av1.y, av1.z, av1.w};
            float b[8] = {bv0.x, bv0.y, bv0.z, bv0.w, bv1.x, bv1.y, bv1.z, bv1.w};
            #pragma unroll
            for (int i = 0; i < 8; i++)
                #pragma unroll
                for (int j = 0; j < 8; j++)
                    acc[i][j] += a[i] * b[j];
        }
        if (more) { stA(buf ^ 1, a0, a1); stB(buf ^ 1, b0, b1); }
        __syncthreads();
        buf ^= 1;
    }

    float bj[8];
    #pragma unroll
    for (int j = 0; j < 8; j++) bj[j] = tb[nB + tx * 8 + j];
    #pragma unroll
    for (int i = 0; i < 8; i++) {
        int gr = mB + ty * 8 + i;
        int nn = gr / 49, pp = gr - nn * 49;
        float* ob = O + (long long)nn * 12544 + pp;
        #pragma unroll
        for (int j = 0; j < 8; j++) {
            float v = fmaxf(acc[i][j] + bj[j], 0.f);
            ob[(nB + tx * 8 + j) * 49] = v;
        }
    }
}

// ---------------- FC split-K reduce + bias + relu + LayerNorm -----------
__global__ void fc_reduce_ln(const float* __restrict__ part, const float* __restrict__ fcb,
                             const float* __restrict__ g, const float* __restrict__ b,
                             float* __restrict__ feats)
{
    __shared__ float sv[1024];
    __shared__ float red[256];
    int n = blockIdx.x, tid = threadIdx.x;
    float s = 0.f;
    #pragma unroll
    for (int i = 0; i < 4; i++) {
        int col = i * 256 + tid;
        float v = fcb[col];
        #pragma unroll
        for (int z = 0; z < 16; z++) v += part[(long long)((z << 9) + n) * 1024 + col];
        v = fmaxf(v, 0.f);
        sv[col] = v;
        s += v;
    }
    red[tid] = s; __syncthreads();
    for (int st = 128; st > 0; st >>= 1) { if (tid < st) red[tid] += red[tid + st]; __syncthreads(); }
    float mu = red[0] * (1.f / 1024.f);
    __syncthreads();
    float q = 0.f;
    #pragma unroll
    for (int i = 0; i < 4; i++) { float d = sv[i * 256 + tid] - mu; q += d * d; }
    red[tid] = q; __syncthreads();
    for (int st = 128; st > 0; st >>= 1) { if (tid < st) red[tid] += red[tid + st]; __syncthreads(); }
    float rstd = rsqrtf(red[0] * (1.f / 1024.f) + CEPS);
    #pragma unroll
    for (int i = 0; i < 4; i++) {
        int col = i * 256 + tid;
        feats[(long long)n * 1280 + col] = (sv[col] - mu) * rstd * g[col] + b[col];
    }
}

// ---------------- box branch: linear(4->256) + LayerNorm ----------------
__global__ void box_ln(const float* __restrict__ nbx, const float* __restrict__ bw,
                       const float* __restrict__ bb, const float* __restrict__ g,
                       const float* __restrict__ be, float* __restrict__ feats)
{
    __shared__ float red[256];
    int n = blockIdx.x, tid = threadIdx.x;
    float a0 = nbx[n * 4 + 0] * 2.f - 1.f;
    float a1 = nbx[n * 4 + 1] * 2.f - 1.f;
    float a2 = nbx[n * 4 + 2] * 2.f - 1.f;
    float a3 = nbx[n * 4 + 3] * 2.f - 1.f;
    const float* w = bw + tid * 4;
    float v = w[0] * a0 + w[1] * a1 + w[2] * a2 + w[3] * a3 + bb[tid];
    red[tid] = v; __syncthreads();
    for (int st = 128; st > 0; st >>= 1) { if (tid < st) red[tid] += red[tid + st]; __syncthreads(); }
    float mu = red[0] * (1.f / 256.f);
    __syncthreads();
    float d = v - mu;
    red[tid] = d * d; __syncthreads();
    for (int st = 128; st > 0; st >>= 1) { if (tid < st) red[tid] += red[tid + st]; __syncthreads(); }
    float rstd = rsqrtf(red[0] * (1.f / 256.f) + CEPS);
    feats[(long long)n * 1280 + 1024 + tid] = (v - mu) * rstd * g[tid] + be[tid];
}

// ---------------- h1[a,b] = relu(U[b] + V[a] + b1) ----------------------
__global__ void build_h1(const float* __restrict__ U, const float* __restrict__ V,
                         const float* __restrict__ b1, float* __restrict__ h1)
{
    int row = blockIdx.x;                 // 0..32767
    int img = row >> 12;
    int a = (row >> 6) & 63;
    int b = row & 63;
    const float* u = U + (long long)(img * 64 + b) * 1280;
    const float* v = V + (long long)(img * 64 + a) * 1280;
    float* o = h1 + (long long)row * 1280;
    for (int i = threadIdx.x; i < 1280; i += 256)
        o[i] = fmaxf(u[i] + v[i] + b1[i], 0.f);
}

// ---------------- final: out[img][j] = sum of 32 M-block partials -------
__global__ void final_reduce(const float* __restrict__ gp, float* __restrict__ out)
{
    int i = blockIdx.x * 256 + threadIdx.x;   // < 10240
    int img = i / 1280, j = i - img * 1280;
    float s = 0.f;
    #pragma unroll
    for (int mb = 0; mb < 32; mb++)
        s += gp[(long long)(img * 32 + mb) * 1280 + j];
    out[i] = s;
}

// ---------------- launch ------------------------------------------------
extern "C" void kernel_launch(void* const* d_in, const int* in_sizes, int n_in,
                              void* d_out, int out_size)
{
    const float* im_feat = (const float*)d_in[0];
    const float* boxes   = (const float*)d_in[1];
    const float* nboxes  = (const float*)d_in[2];
    const float* proj_w  = (const float*)d_in[3];
    const float* proj_b  = (const float*)d_in[4];
    const float* conv_w  = (const float*)d_in[5];
    const float* conv_b  = (const float*)d_in[6];
    const float* bn_g = (const float*)d_in[7];
    const float* bn_b = (const float*)d_in[8];
    const float* bn_m = (const float*)d_in[9];
    const float* bn_v = (const float*)d_in[10];
    const float* fc_w = (const float*)d_in[11];
    const float* fc_b = (const float*)d_in[12];
    const float* ln1_g = (const float*)d_in[13];
    const float* ln1_b = (const float*)d_in[14];
    const float* box_w = (const float*)d_in[15];
    const float* box_b = (const float*)d_in[16];
    const float* ln2_g = (const float*)d_in[17];
    const float* ln2_b = (const float*)d_in[18];
    const float* g1_w = (const float*)d_in[19];
    const float* g1_b = (const float*)d_in[20];
    const float* g2_w = (const float*)d_in[21];
    const float* g2_b = (const float*)d_in[22];
    const float* g3_w = (const float*)d_in[23];
    const float* g3_b = (const float*)d_in[24];
    float* out = (float*)d_out;

    float *p_imT, *p_x, *p_wT, *p_tb, *p_r, *p_r1, *p_fcp, *p_feats, *p_U, *p_V, *p_h1, *p_h2, *p_gp;
    cudaGetSymbolAddress((void**)&p_imT, d_imT);
    cudaGetSymbolAddress((void**)&p_x, d_x);
    cudaGetSymbolAddress((void**)&p_wT, d_wT);
    cudaGetSymbolAddress((void**)&p_tb, d_tb);
    cudaGetSymbolAddress((void**)&p_r, d_r);
    cudaGetSymbolAddress((void**)&p_r1, d_r1);
    cudaGetSymbolAddress((void**)&p_fcp, d_fcp);
    cudaGetSymbolAddress((void**)&p_feats, d_feats);
    cudaGetSymbolAddress((void**)&p_U, d_U);
    cudaGetSymbolAddress((void**)&p_V, d_V);
    cudaGetSymbolAddress((void**)&p_h1, d_h1);
    cudaGetSymbolAddress((void**)&p_h2, d_h2);
    cudaGetSymbolAddress((void**)&p_gp, d_gp);

    // 1) transpose im_feat -> [b][hw][cin]
    transpose_bchw<<<dim3(8, 64, 8), dim3(32, 8)>>>(im_feat, p_imT);
    // 2) fold BN into conv weights/bias
    prep_convw<<<9216, 256>>>(conv_w, bn_g, bn_v, p_wT);
    prep_tb<<<1, 256>>>(conv_b, bn_g, bn_b, bn_m, bn_v, p_tb);
    // 3) 1x1 projection: [2048 rows x 1024] = imT @ proj_w^T + proj_b
    gemm128<1><<<dim3(16, 8, 1), 256>>>(p_imT, 2048, 0, proj_w, 2048, 0, proj_b,
                                        p_x, 1024, 0, 2048, nullptr);
    // 4) ROIAlign gather
    roialign_kernel<<<25088, 256>>>(p_x, boxes, p_r);
    // 5) conv3x3 + BN + ReLU (implicit GEMM), writes channel-major flat
    conv_gemm<<<dim3(196, 2), 256>>>(p_r, p_wT, p_tb, p_r1);
    // 6) FC (split-K = 16)
    gemm128<0><<<dim3(4, 8, 16), 256>>>(p_r1, 12544, 784, fc_w, 12544, 784, nullptr,
                                        p_fcp, 1024, 512LL * 1024, 784, nullptr);
    // 7) reduce + bias + relu + LN1
    fc_reduce_ln<<<512, 256>>>(p_fcp, fc_b, ln1_g, ln1_b, p_feats);
    // 8) box branch
    box_ln<<<512, 256>>>(nboxes, box_w, box_b, ln2_g, ln2_b, p_feats);
    // 9) U = feats @ g1a^T ; V = feats @ g1b^T
    gemm128<0><<<dim3(4, 10, 1), 256>>>(p_feats, 1280, 0, g1_w, 2560, 0, nullptr,
                                        p_U, 1280, 0, 1280, nullptr);
    gemm128<0><<<dim3(4, 10, 1), 256>>>(p_feats, 1280, 0, g1_w + 1280, 2560, 0, nullptr,
                                        p_V, 1280, 0, 1280, nullptr);
    // 10) h1 = relu(U[b] + V[a] + b1)
    build_h1<<<32768, 256>>>(p_U, p_V, g1_b, p_h1);
    // 11) h2 = relu(h1 @ g2^T + b2)
    gemm128<2><<<dim3(256, 10, 1), 256>>>(p_h1, 1280, 0, g2_w, 1280, 0, g2_b,
                                          p_h2, 1280, 0, 1280, nullptr);
    // 12) g3 + relu + fused per-Mblock column sums
    gemm128<3><<<dim3(256, 10, 1), 256>>>(p_h2, 1280, 0, g3_w, 1280, 0, g3_b,
                                          p_h1, 1280, 0, 1280, p_gp);
    // 13) final reduce across M-blocks per image
    final_reduce<<<40, 256>>>(p_gp, out);
}

// round 3
// speedup vs baseline: 1.0487x; 1.0487x over previous
#include <cuda_runtime.h>

#define CEPS 1e-5f
typedef unsigned long long u64;

// ---------------- f32x2 packed FMA helpers (Blackwell FFMA2) -------------
__device__ __forceinline__ u64 splat2(float a) {
    u64 r;
    asm("mov.b64 %0, {%1, %1};" : "=l"(r) : "r"(__float_as_uint(a)));
    return r;
}
__device__ __forceinline__ void fma2(u64& c, u64 a, u64 b) {
    asm("fma.rn.f32x2 %0, %1, %2, %0;" : "+l"(c) : "l"(a), "l"(b));
}
__device__ __forceinline__ float2 unpack2(u64 v) {
    float2 f;
    asm("mov.b64 {%0, %1}, %2;" : "=f"(f.x), "=f"(f.y) : "l"(v));
    return f;
}

// ---------------- device scratch (no allocation allowed) ----------------
__device__ float d_imT[8 * 256 * 2048];          // [b][hw][cin]
__device__ float d_x[8 * 256 * 1024];            // [b][hw][c2]
__device__ float d_wT[9 * 1024 * 256];           // [tap][ci][o] BN-folded
__device__ float d_tb[256];                      // folded conv bias
__device__ float d_r[512 * 49 * 1024];           // roi tiles [roi][pix][c]
__device__ float d_r1[512 * 12544];              // conv out, flat (o*49+p)
__device__ float d_fcp[16 * 512 * 1024];         // FC split-K partials
__device__ float d_feats[512 * 1280];
__device__ float d_UV[2 * 512 * 1280];           // [0]=U, [1]=V
__device__ float d_h1[32768u * 1280u];
__device__ float d_h2[32768u * 1280u];
__device__ float d_gp[256 * 1280];               // g3 per-Mblock col sums

// ---------------- transpose im_feat [8][2048][256] -> [8][256][2048] ----
__global__ void transpose_bchw(const float* __restrict__ in, float* __restrict__ out) {
    __shared__ float tile[32][33];
    int b = blockIdx.z;
    int p0 = blockIdx.x * 32;   // hw
    int c0 = blockIdx.y * 32;   // channel
    int tx = threadIdx.x, ty = threadIdx.y;
    const float* ip = in + (long long)b * 2048 * 256;
    #pragma unroll
    for (int i = 0; i < 32; i += 8)
        tile[ty + i][tx] = ip[(c0 + ty + i) * 256 + p0 + tx];
    __syncthreads();
    float* op = out + (long long)b * 256 * 2048;
    #pragma unroll
    for (int i = 0; i < 32; i += 8)
        op[(p0 + ty + i) * 2048 + c0 + tx] = tile[tx][ty + i];
}

// ---------------- conv weight prep: wT[t][ci][o] = conv_w[o][ci][t]*s[o] ---
__global__ void prep_convw(const float* __restrict__ cw, const float* __restrict__ g,
                           const float* __restrict__ v, float* __restrict__ wT) {
    int i = blockIdx.x * 256 + threadIdx.x;   // < 9*1024*256
    int o = i & 255;
    int ci = (i >> 8) & 1023;
    int t = i >> 18;
    float s = g[o] * rsqrtf(v[o] + CEPS);
    wT[i] = cw[o * 9216 + ci * 9 + t] * s;
}

__global__ void prep_tb(const float* __restrict__ cb, const float* __restrict__ g,
                        const float* __restrict__ b, const float* __restrict__ m,
                        const float* __restrict__ v, float* __restrict__ tb) {
    int o = threadIdx.x;
    float s = g[o] * rsqrtf(v[o] + CEPS);
    tb[o] = (cb[o] - m[o]) * s + b[o];
}

// ---------------- generic GEMM: C = A[M,K] @ B[N,K]^T (+bias)(+relu) -----
// EPI: 0 store, 1 +bias store, 2 +bias relu store, 3 +bias relu colsum only
// FFMA2 inner kernel: accumulators packed in pairs along N.
template<int EPI>
__global__ void __launch_bounds__(256, 2) gemm128(
    const float* __restrict__ A, int lda, long long aZ,
    const float* __restrict__ B, int ldb, long long bZ,
    const float* __restrict__ bias,
    float* __restrict__ C, int ldc, long long cZ,
    int K, float* __restrict__ colsum)
{
    __shared__ __align__(16) float As[2][16][132];
    __shared__ __align__(16) float Bs[2][16][132];
    const int tid = threadIdx.x;
    const int z = blockIdx.z;
    const int mB = blockIdx.x * 128, nB = blockIdx.y * 128;
    A += (long long)z * aZ;
    B += (long long)z * bZ;

    const int lr = tid >> 2;            // 0..63
    const int lk = (tid & 3) << 2;      // 0,4,8,12
    const float* Ag0 = A + (long long)(mB + lr) * lda + lk;
    const float* Ag1 = Ag0 + 64LL * lda;
    const float* Bg0 = B + (long long)(nB + lr) * ldb + lk;
    const float* Bg1 = Bg0 + 64LL * ldb;

    const int ty = tid >> 4, tx = tid & 15;
    u64 acc2[8][4];
    #pragma unroll
    for (int i = 0; i < 8; i++)
        #pragma unroll
        for (int j = 0; j < 4; j++) acc2[i][j] = 0ull;

    // initial fill
    {
        float4 a0 = *(const float4*)Ag0;
        float4 a1 = *(const float4*)Ag1;
        float4 b0 = *(const float4*)Bg0;
        float4 b1 = *(const float4*)Bg1;
        As[0][lk + 0][lr] = a0.x; As[0][lk + 1][lr] = a0.y; As[0][lk + 2][lr] = a0.z; As[0][lk + 3][lr] = a0.w;
        As[0][lk + 0][lr + 64] = a1.x; As[0][lk + 1][lr + 64] = a1.y; As[0][lk + 2][lr + 64] = a1.z; As[0][lk + 3][lr + 64] = a1.w;
        Bs[0][lk + 0][lr] = b0.x; Bs[0][lk + 1][lr] = b0.y; Bs[0][lk + 2][lr] = b0.z; Bs[0][lk + 3][lr] = b0.w;
        Bs[0][lk + 0][lr + 64] = b1.x; Bs[0][lk + 1][lr + 64] = b1.y; Bs[0][lk + 2][lr + 64] = b1.z; Bs[0][lk + 3][lr + 64] = b1.w;
    }
    __syncthreads();

    int buf = 0;
    for (int kt = 0; kt < K; kt += 16) {
        float4 a0, a1, b0, b1;
        const bool more = (kt + 16) < K;
        if (more) {
            a0 = *(const float4*)(Ag0 + kt + 16);
            a1 = *(const float4*)(Ag1 + kt + 16);
            b0 = *(const float4*)(Bg0 + kt + 16);
            b1 = *(const float4*)(Bg1 + kt + 16);
        }
        #pragma unroll
        for (int k = 0; k < 16; k++) {
            float4 av0 = *(const float4*)&As[buf][k][ty * 8];
            float4 av1 = *(const float4*)&As[buf][k][ty * 8 + 4];
            ulonglong2 bq0 = *(const ulonglong2*)&Bs[buf][k][tx * 8];
            ulonglong2 bq1 = *(const ulonglong2*)&Bs[buf][k][tx * 8 + 4];
            u64 bb[4] = {bq0.x, bq0.y, bq1.x, bq1.y};
            u64 aa[8];
            aa[0] = splat2(av0.x); aa[1] = splat2(av0.y);
            aa[2] = splat2(av0.z); aa[3] = splat2(av0.w);
            aa[4] = splat2(av1.x); aa[5] = splat2(av1.y);
            aa[6] = splat2(av1.z); aa[7] = splat2(av1.w);
            #pragma unroll
            for (int i = 0; i < 8; i++)
                #pragma unroll
                for (int j = 0; j < 4; j++)
                    fma2(acc2[i][j], aa[i], bb[j]);
        }
        if (more) {
            int nb2 = buf ^ 1;
            As[nb2][lk + 0][lr] = a0.x; As[nb2][lk + 1][lr] = a0.y; As[nb2][lk + 2][lr] = a0.z; As[nb2][lk + 3][lr] = a0.w;
            As[nb2][lk + 0][lr + 64] = a1.x; As[nb2][lk + 1][lr + 64] = a1.y; As[nb2][lk + 2][lr + 64] = a1.z; As[nb2][lk + 3][lr + 64] = a1.w;
            Bs[nb2][lk + 0][lr] = b0.x; Bs[nb2][lk + 1][lr] = b0.y; Bs[nb2][lk + 2][lr] = b0.z; Bs[nb2][lk + 3][lr] = b0.w;
            Bs[nb2][lk + 0][lr + 64] = b1.x; Bs[nb2][lk + 1][lr + 64] = b1.y; Bs[nb2][lk + 2][lr + 64] = b1.z; Bs[nb2][lk + 3][lr + 64] = b1.w;
        }
        __syncthreads();
        buf ^= 1;
    }

    // unpack accumulators
    float acc[8][8];
    #pragma unroll
    for (int i = 0; i < 8; i++)
        #pragma unroll
        for (int j = 0; j < 4; j++) {
            float2 p = unpack2(acc2[i][j]);
            acc[i][2 * j] = p.x;
            acc[i][2 * j + 1] = p.y;
        }

    const int colBase = nB + tx * 8;
    if (EPI == 3) {
        float bj[8];
        #pragma unroll
        for (int j = 0; j < 8; j++) bj[j] = bias[colBase + j];
        float cs[8];
        #pragma unroll
        for (int j = 0; j < 8; j++) {
            cs[j] = 0.f;
            #pragma unroll
            for (int i = 0; i < 8; i++) cs[j] += fmaxf(acc[i][j] + bj[j], 0.f);
        }
        float* red = &As[0][0][0];   // safe: loop ended with __syncthreads
        #pragma unroll
        for (int j = 0; j < 8; j++) red[ty * 128 + tx * 8 + j] = cs[j];
        __syncthreads();
        for (int s = 8; s > 0; s >>= 1) {
            if (ty < s) {
                #pragma unroll
                for (int j = 0; j < 8; j++)
                    red[ty * 128 + tx * 8 + j] += red[(ty + s) * 128 + tx * 8 + j];
            }
            __syncthreads();
        }
        if (ty == 0) {
            #pragma unroll
            for (int j = 0; j < 8; j++)
                colsum[(long long)blockIdx.x * (gridDim.y * 128) + colBase + j] = red[tx * 8 + j];
        }
    } else {
        float bj[8];
        #pragma unroll
        for (int j = 0; j < 8; j++) bj[j] = (EPI >= 1) ? bias[colBase + j] : 0.f;
        float* Cz = C + (long long)z * cZ;
        #pragma unroll
        for (int i = 0; i < 8; i++) {
            long long r = mB + ty * 8 + i;
            float o[8];
            #pragma unroll
            for (int j = 0; j < 8; j++) {
                float v = acc[i][j] + bj[j];
                if (EPI == 2) v = fmaxf(v, 0.f);
                o[j] = v;
            }
            *(float4*)&Cz[r * ldc + colBase] = make_float4(o[0], o[1], o[2], o[3]);
            *(float4*)&Cz[r * ldc + colBase + 4] = make_float4(o[4], o[5], o[6], o[7]);
        }
    }
}

// ---------------- ROIAlign gather: one block per (roi, bin) -------------
__global__ void roialign_kernel(const float* __restrict__ x,     // [8][256][1024]
                                const float* __restrict__ boxes, // [512][4]
                                float* __restrict__ out)         // [512][49][1024]
{
    int blk = blockIdx.x;     // 0..25087
    int n = blk / 49;
    int bin = blk - n * 49;
    int by = bin / 7, bx = bin - by * 7;
    int b = n >> 6;
    const float* roi = boxes + n * 4;
    float x1 = roi[0] * (1.f / 32.f) - 0.5f;
    float y1 = roi[1] * (1.f / 32.f) - 0.5f;
    float bw = (roi[2] - roi[0]) * (1.f / 32.f) * (1.f / 7.f);
    float bh = (roi[3] - roi[1]) * (1.f / 32.f) * (1.f / 7.f);

    int pidx[16];
    float pw[16];
    int cnt = 0;
    #pragma unroll
    for (int sy = 0; sy < 2; sy++) {
        float ys = y1 + bh * ((float)by + (sy + 0.5f) * 0.5f);
        bool vy = (ys >= -1.f) && (ys <= 16.f);
        float v = fmaxf(ys, 0.f);
        int lo = (int)floorf(v);
        int yl, yh; float wy;
        if (lo >= 15) { yl = 15; yh = 15; wy = 0.f; }
        else { yl = lo; yh = lo + 1; wy = v - (float)lo; }
        #pragma unroll
        for (int sx = 0; sx < 2; sx++) {
            float xs = x1 + bw * ((float)bx + (sx + 0.5f) * 0.5f);
            bool vx = (xs >= -1.f) && (xs <= 16.f);
            float u = fmaxf(xs, 0.f);
            int lo2 = (int)floorf(u);
            int xl, xh; float wx;
            if (lo2 >= 15) { xl = 15; xh = 15; wx = 0.f; }
            else { xl = lo2; xh = lo2 + 1; wx = u - (float)lo2; }
            float m = (vy && vx) ? 0.25f : 0.f;
            pidx[cnt] = yl * 16 + xl; pw[cnt] = (1.f - wy) * (1.f - wx) * m; cnt++;
            pidx[cnt] = yl * 16 + xh; pw[cnt] = (1.f - wy) * wx * m;         cnt++;
            pidx[cnt] = yh * 16 + xl; pw[cnt] = wy * (1.f - wx) * m;         cnt++;
            pidx[cnt] = yh * 16 + xh; pw[cnt] = wy * wx * m;                 cnt++;
        }
    }

    const float* xb = x + ((long long)b << 18);   // b*256*1024
    int c = threadIdx.x * 4;
    float4 acc = make_float4(0.f, 0.f, 0.f, 0.f);
    #pragma unroll
    for (int t = 0; t < 16; t++) {
        float4 vv = *(const float4*)(xb + (pidx[t] << 10) + c);
        acc.x += pw[t] * vv.x; acc.y += pw[t] * vv.y;
        acc.z += pw[t] * vv.z; acc.w += pw[t] * vv.w;
    }
    *(float4*)(out + ((long long)blk << 10) + c) = acc;
}

// ---------------- conv3x3 implicit GEMM (BN+ReLU folded), FFMA2 ----------
__global__ void __launch_bounds__(256, 2) conv_gemm(
    const float* __restrict__ R,    // [512][49][1024]
    const float* __restrict__ wT,   // [9][1024][256]
    const float* __restrict__ tb,   // [256]
    float* __restrict__ O)          // [512][12544] flat (o*49+p)
{
    __shared__ __align__(16) float As[2][16][132];
    __shared__ __align__(16) float Bs[2][16][132];
    const int tid = threadIdx.x;
    const int mB = blockIdx.x * 128, nB = blockIdx.y * 128;
    const int lr = tid >> 2, lk = (tid & 3) << 2;
    const int bk = tid >> 4, bn = (tid & 15) << 3;
    const int ty = tid >> 4, tx = tid & 15;

    int off0[9], off1[9];
    {
        int gr0 = mB + lr, gr1 = gr0 + 64;
        int n0 = gr0 / 49, p0 = gr0 - n0 * 49, y0 = p0 / 7, x0 = p0 - y0 * 7;
        int n1 = gr1 / 49, p1 = gr1 - n1 * 49, y1 = p1 / 7, x1 = p1 - y1 * 7;
        #pragma unroll
        for (int t = 0; t < 9; t++) {
            int kh = t / 3 - 1, kw = t % 3 - 1;
            int iy = y0 + kh, ix = x0 + kw;
            off0[t] = (iy >= 0 && iy < 7 && ix >= 0 && ix < 7) ? ((n0 * 49 + iy * 7 + ix) << 10) : -1;
            iy = y1 + kh; ix = x1 + kw;
            off1[t] = (iy >= 0 && iy < 7 && ix >= 0 && ix < 7) ? ((n1 * 49 + iy * 7 + ix) << 10) : -1;
        }
    }

    u64 acc2[8][4];
    #pragma unroll
    for (int i = 0; i < 8; i++)
        #pragma unroll
        for (int j = 0; j < 4; j++) acc2[i][j] = 0ull;

    const float4 z4 = make_float4(0.f, 0.f, 0.f, 0.f);
    auto ldA = [&](int q, float4& a0, float4& a1) {
        int t = q >> 6;
        int kk = ((q & 63) << 4) + lk;
        a0 = (off0[t] >= 0) ? *(const float4*)(R + off0[t] + kk) : z4;
        a1 = (off1[t] >= 0) ? *(const float4*)(R + off1[t] + kk) : z4;
    };
    auto ldB = [&](int q, float4& b0, float4& b1) {
        int t = q >> 6;
        int kk = ((q & 63) << 4) + bk;
        const float* p = wT + (t << 18) + kk * 256 + nB + bn;
        b0 = *(const float4*)p;
        b1 = *(const float4*)(p + 4);
    };
    auto stA = [&](int bu, float4 a0, float4 a1) {
        As[bu][lk + 0][lr] = a0.x; As[bu][lk + 1][lr] = a0.y; As[bu][lk + 2][lr] = a0.z; As[bu][lk + 3][lr] = a0.w;
        As[bu][lk + 0][lr + 64] = a1.x; As[bu][lk + 1][lr + 64] = a1.y; As[bu][lk + 2][lr + 64] = a1.z; As[bu][lk + 3][lr + 64] = a1.w;
    };
    auto stB = [&](int bu, float4 b0, float4 b1) {
        *(float4*)&Bs[bu][bk][bn] = b0;
        *(float4*)&Bs[bu][bk][bn + 4] = b1;
    };

    {
        float4 a0, a1, b0, b1;
        ldA(0, a0, a1); ldB(0, b0, b1);
        stA(0, a0, a1); stB(0, b0, b1);
    }
    __syncthreads();

    int buf = 0;
    for (int q = 0; q < 576; q++) {
        float4 a0, a1, b0, b1;
        const bool more = (q + 1) < 576;
        if (more) { ldA(q + 1, a0, a1); ldB(q + 1, b0, b1); }
        #pragma unroll
        for (int k = 0; k < 16; k++) {
            float4 av0 = *(const float4*)&As[buf][k][ty * 8];
            float4 av1 = *(const float4*)&As[buf][k][ty * 8 + 4];
            ulonglong2 bq0 = *(const ulonglong2*)&Bs[buf][k][tx * 8];
            ulonglong2 bq1 = *(const ulonglong2*)&Bs[buf][k][tx * 8 + 4];
            u64 bb[4] = {bq0.x, bq0.y, bq1.x, bq1.y};
            u64 aa[8];
            aa[0] = splat2(av0.x); aa[1] = splat2(av0.y);
            aa[2] = splat2(av0.z); aa[3] = splat2(av0.w);
            aa[4] = splat2(av1.x); aa[5] = splat2(av1.y);
            aa[6] = splat2(av1.z); aa[7] = splat2(av1.w);
            #pragma unroll
            for (int i = 0; i < 8; i++)
                #pragma unroll
                for (int j = 0; j < 4; j++)
                    fma2(acc2[i][j], aa[i], bb[j]);
        }
        if (more) { stA(buf ^ 1, a0, a1); stB(buf ^ 1, b0, b1); }
        __syncthreads();
        buf ^= 1;
    }

    float acc[8][8];
    #pragma unroll
    for (int i = 0; i < 8; i++)
        #pragma unroll
        for (int j = 0; j < 4; j++) {
            float2 p = unpack2(acc2[i][j]);
            acc[i][2 * j] = p.x;
            acc[i][2 * j + 1] = p.y;
        }

    float bj[8];
    #pragma unroll
    for (int j = 0; j < 8; j++) bj[j] = tb[nB + tx * 8 + j];
    #pragma unroll
    for (int i = 0; i < 8; i++) {
        int gr = mB + ty * 8 + i;
        int nn = gr / 49, pp = gr - nn * 49;
        float* ob = O + (long long)nn * 12544 + pp;
        #pragma unroll
        for (int j = 0; j < 8; j++) {
            float v = fmaxf(acc[i][j] + bj[j], 0.f);
            ob[(nB + tx * 8 + j) * 49] = v;
        }
    }
}

// ---------------- FC split-K reduce + bias + relu + LayerNorm -----------
__global__ void fc_reduce_ln(const float* __restrict__ part, const float* __restrict__ fcb,
                             const float* __restrict__ g, const float* __restrict__ b,
                             float* __restrict__ feats)
{
    __shared__ float sv[1024];
    __shared__ float red[256];
    int n = blockIdx.x, tid = threadIdx.x;
    float s = 0.f;
    #pragma unroll
    for (int i = 0; i < 4; i++) {
        int col = i * 256 + tid;
        float v = fcb[col];
        #pragma unroll
        for (int z = 0; z < 16; z++) v += part[(long long)((z << 9) + n) * 1024 + col];
        v = fmaxf(v, 0.f);
        sv[col] = v;
        s += v;
    }
    red[tid] = s; __syncthreads();
    for (int st = 128; st > 0; st >>= 1) { if (tid < st) red[tid] += red[tid + st]; __syncthreads(); }
    float mu = red[0] * (1.f / 1024.f);
    __syncthreads();
    float q = 0.f;
    #pragma unroll
    for (int i = 0; i < 4; i++) { float d = sv[i * 256 + tid] - mu; q += d * d; }
    red[tid] = q; __syncthreads();
    for (int st = 128; st > 0; st >>= 1) { if (tid < st) red[tid] += red[tid + st]; __syncthreads(); }
    float rstd = rsqrtf(red[0] * (1.f / 1024.f) + CEPS);
    #pragma unroll
    for (int i = 0; i < 4; i++) {
        int col = i * 256 + tid;
        feats[(long long)n * 1280 + col] = (sv[col] - mu) * rstd * g[col] + b[col];
    }
}

// ---------------- box branch: linear(4->256) + LayerNorm ----------------
__global__ void box_ln(const float* __restrict__ nbx, const float* __restrict__ bw,
                       const float* __restrict__ bb, const float* __restrict__ g,
                       const float* __restrict__ be, float* __restrict__ feats)
{
    __shared__ float red[256];
    int n = blockIdx.x, tid = threadIdx.x;
    float a0 = nbx[n * 4 + 0] * 2.f - 1.f;
    float a1 = nbx[n * 4 + 1] * 2.f - 1.f;
    float a2 = nbx[n * 4 + 2] * 2.f - 1.f;
    float a3 = nbx[n * 4 + 3] * 2.f - 1.f;
    const float* w = bw + tid * 4;
    float v = w[0] * a0 + w[1] * a1 + w[2] * a2 + w[3] * a3 + bb[tid];
    red[tid] = v; __syncthreads();
    for (int st = 128; st > 0; st >>= 1) { if (tid < st) red[tid] += red[tid + st]; __syncthreads(); }
    float mu = red[0] * (1.f / 256.f);
    __syncthreads();
    float d = v - mu;
    red[tid] = d * d; __syncthreads();
    for (int st = 128; st > 0; st >>= 1) { if (tid < st) red[tid] += red[tid + st]; __syncthreads(); }
    float rstd = rsqrtf(red[0] * (1.f / 256.f) + CEPS);
    feats[(long long)n * 1280 + 1024 + tid] = (v - mu) * rstd * g[tid] + be[tid];
}

// ---------------- h1[a,b] = relu(U[b] + V[a] + b1) ----------------------
__global__ void build_h1(const float* __restrict__ UV, const float* __restrict__ b1,
                         float* __restrict__ h1)
{
    int row = blockIdx.x;                 // 0..32767
    int img = row >> 12;
    int a = (row >> 6) & 63;
    int b = row & 63;
    const float* u = UV + (long long)(img * 64 + b) * 1280;
    const float* v = UV + (long long)(512 + img * 64 + a) * 1280;
    float* o = h1 + (long long)row * 1280;
    for (int i = threadIdx.x; i < 1280; i += 256)
        o[i] = fmaxf(u[i] + v[i] + b1[i], 0.f);
}

// ---------------- final: out[img][j] = sum of 32 M-block partials -------
__global__ void final_reduce(const float* __restrict__ gp, float* __restrict__ out)
{
    int i = blockIdx.x * 256 + threadIdx.x;   // < 10240
    int img = i / 1280, j = i - img * 1280;
    float s = 0.f;
    #pragma unroll
    for (int mb = 0; mb < 32; mb++)
        s += gp[(long long)(img * 32 + mb) * 1280 + j];
    out[i] = s;
}

// ---------------- launch ------------------------------------------------
extern "C" void kernel_launch(void* const* d_in, const int* in_sizes, int n_in,
                              void* d_out, int out_size)
{
    const float* im_feat = (const float*)d_in[0];
    const float* boxes   = (const float*)d_in[1];
    const float* nboxes  = (const float*)d_in[2];
    const float* proj_w  = (const float*)d_in[3];
    const float* proj_b  = (const float*)d_in[4];
    const float* conv_w  = (const float*)d_in[5];
    const float* conv_b  = (const float*)d_in[6];
    const float* bn_g = (const float*)d_in[7];
    const float* bn_b = (const float*)d_in[8];
    const float* bn_m = (const float*)d_in[9];
    const float* bn_v = (const float*)d_in[10];
    const float* fc_w = (const float*)d_in[11];
    const float* fc_b = (const float*)d_in[12];
    const float* ln1_g = (const float*)d_in[13];
    const float* ln1_b = (const float*)d_in[14];
    const float* box_w = (const float*)d_in[15];
    const float* box_b = (const float*)d_in[16];
    const float* ln2_g = (const float*)d_in[17];
    const float* ln2_b = (const float*)d_in[18];
    const float* g1_w = (const float*)d_in[19];
    const float* g1_b = (const float*)d_in[20];
    const float* g2_w = (const float*)d_in[21];
    const float* g2_b = (const float*)d_in[22];
    const float* g3_w = (const float*)d_in[23];
    const float* g3_b = (const float*)d_in[24];
    float* out = (float*)d_out;

    float *p_imT, *p_x, *p_wT, *p_tb, *p_r, *p_r1, *p_fcp, *p_feats, *p_UV, *p_h1, *p_h2, *p_gp;
    cudaGetSymbolAddress((void**)&p_imT, d_imT);
    cudaGetSymbolAddress((void**)&p_x, d_x);
    cudaGetSymbolAddress((void**)&p_wT, d_wT);
    cudaGetSymbolAddress((void**)&p_tb, d_tb);
    cudaGetSymbolAddress((void**)&p_r, d_r);
    cudaGetSymbolAddress((void**)&p_r1, d_r1);
    cudaGetSymbolAddress((void**)&p_fcp, d_fcp);
    cudaGetSymbolAddress((void**)&p_feats, d_feats);
    cudaGetSymbolAddress((void**)&p_UV, d_UV);
    cudaGetSymbolAddress((void**)&p_h1, d_h1);
    cudaGetSymbolAddress((void**)&p_h2, d_h2);
    cudaGetSymbolAddress((void**)&p_gp, d_gp);

    // 1) transpose im_feat -> [b][hw][cin]
    transpose_bchw<<<dim3(8, 64, 8), dim3(32, 8)>>>(im_feat, p_imT);
    // 2) fold BN into conv weights/bias
    prep_convw<<<9216, 256>>>(conv_w, bn_g, bn_v, p_wT);
    prep_tb<<<1, 256>>>(conv_b, bn_g, bn_b, bn_m, bn_v, p_tb);
    // 3) 1x1 projection: [2048 rows x 1024] = imT @ proj_w^T + proj_b
    gemm128<1><<<dim3(16, 8, 1), 256>>>(p_imT, 2048, 0, proj_w, 2048, 0, proj_b,
                                        p_x, 1024, 0, 2048, nullptr);
    // 4) ROIAlign gather
    roialign_kernel<<<25088, 256>>>(p_x, boxes, p_r);
    // 5) conv3x3 + BN + ReLU (implicit GEMM), writes channel-major flat
    conv_gemm<<<dim3(196, 2), 256>>>(p_r, p_wT, p_tb, p_r1);
    // 6) FC (split-K = 16)
    gemm128<0><<<dim3(4, 8, 16), 256>>>(p_r1, 12544, 784, fc_w, 12544, 784, nullptr,
                                        p_fcp, 1024, 512LL * 1024, 784, nullptr);
    // 7) reduce + bias + relu + LN1
    fc_reduce_ln<<<512, 256>>>(p_fcp, fc_b, ln1_g, ln1_b, p_feats);
    // 8) box branch
    box_ln<<<512, 256>>>(nboxes, box_w, box_b, ln2_g, ln2_b, p_feats);
    // 9) U = feats @ g1a^T ; V = feats @ g1b^T  (single z=2 launch)
    gemm128<0><<<dim3(4, 10, 2), 256>>>(p_feats, 1280, 0, g1_w, 2560, 1280, nullptr,
                                        p_UV, 1280, 512LL * 1280, 1280, nullptr);
    // 10) h1 = relu(U[b] + V[a] + b1)
    build_h1<<<32768, 256>>>(p_UV, g1_b, p_h1);
    // 11) h2 = relu(h1 @ g2^T + b2)
    gemm128<2><<<dim3(256, 10, 1), 256>>>(p_h1, 1280, 0, g2_w, 1280, 0, g2_b,
                                          p_h2, 1280, 0, 1280, nullptr);
    // 12) g3 + relu + fused per-Mblock column sums
    gemm128<3><<<dim3(256, 10, 1), 256>>>(p_h2, 1280, 0, g3_w, 1280, 0, g3_b,
                                          p_h1, 1280, 0, 1280, p_gp);
    // 13) final reduce across M-blocks per image
    final_reduce<<<40, 256>>>(p_gp, out);
}